// round 9
// baseline (speedup 1.0000x reference)
#include <cuda_runtime.h>
#include <cstdint>

#define BATCH 32768

// ---------------- scratch (static device globals; no allocs allowed) ----------------
__device__ __align__(16) float g_buf0[BATCH * 1024];
__device__ __align__(16) float g_buf1[BATCH * 1024];
__device__ __align__(16) float g_x4n [BATCH * 512];
__device__ __align__(16) float g_xn  [BATCH * 256];   // tf32+K-permuted node_x
__device__ __align__(16) float g_xl  [BATCH * 16];    // tf32+K-permuted layer_x
__device__ __align__(16) float g_wt  [2428928];       // tf32+K-permuted weights (8 mats)
__device__ __align__(16) float g_wn[512];
__device__ __align__(16) float g_wl[512];
__device__ float g_sc[2];   // [0]=bn (mean of nb5), [1]=bl (wreg . lb5)

// weight offsets inside g_wt
#define OFF_NW1 0
#define OFF_NW2 65536
#define OFF_NW3 196608
#define OFF_NW4 720896
#define OFF_LW1 1245184
#define OFF_LW2 1249280
#define OFF_LW3 1380352
#define OFF_LW4 1904640

// K-permutation within each 8-wide chunk: stored order [0,4,1,5,2,6,3,7].
// q[w] = original col held at permuted slot w;  p[c] = slot where original col c lives.
__device__ __forceinline__ int perm_q(int w) { return (w & 1) ? ((w >> 1) + 4) : (w >> 1); }
__device__ __forceinline__ int perm_p(int c) { return (c < 4) ? (c << 1) : ((c << 1) - 7); }

// cvt.rna.tf32.f32: destination is a .b32 register -> "=r".
__device__ __forceinline__ uint32_t f32_to_tf32_rna(float x) {
    uint32_t r;
    asm("cvt.rna.tf32.f32 %0, %1;" : "=r"(r) : "f"(x));
    return r;
}
__device__ __forceinline__ float tf32r(float x) {
    return __uint_as_float(f32_to_tf32_rna(x));
}

__device__ __forceinline__ uint32_t smem_u32(const void* p) {
    uint32_t a;
    asm("{ .reg .u64 t; cvta.to.shared.u64 t, %1; cvt.u32.u64 %0, t; }" : "=r"(a) : "l"(p));
    return a;
}

// cp.async 16B with register src-size (0 => zero-fill 16B)
__device__ __forceinline__ void cp16(uint32_t dst, const void* src, int src_size) {
    asm volatile("cp.async.cg.shared.global [%0], [%1], 16, %2;"
                 :: "r"(dst), "l"(src), "r"(src_size));
}
#define CP_COMMIT() asm volatile("cp.async.commit_group;" ::: "memory")
#define CP_WAIT0()  asm volatile("cp.async.wait_group 0;" ::: "memory")
#define CP_WAIT1()  asm volatile("cp.async.wait_group 1;" ::: "memory")

// ---------------- tf32-RNA + K-permute prepass (elementwise gather) ----------------
// dst[i] = tf32r(src[(i&~7) | q[i&7]]);  requires row length (K) % 8 == 0.
__global__ void cvt_perm_kernel(const float* __restrict__ src, float* __restrict__ dst, int n)
{
    int i = blockIdx.x * 256 + threadIdx.x;
    if (i < n) {
        int j = (i & ~7) | perm_q(i & 7);
        dst[i] = tf32r(src[j]);
    }
}

// ---------------- head-collapse precompute (stores into permuted layout) ----------------
// w_n[k] = mean_o nW5[o,k]; w_l[k] = sum_o wreg[o]*lW5[o,k]
__global__ void precompute_head(const float* __restrict__ nW5, const float* __restrict__ nb5,
                                const float* __restrict__ lW5, const float* __restrict__ lb5,
                                const float* __restrict__ wreg)
{
    int k = threadIdx.x;                // 512 threads, k = ORIGINAL col index
    float s1 = 0.f, s2 = 0.f;
    #pragma unroll 4
    for (int o = 0; o < 256; ++o) {
        s1 += nW5[o * 512 + k];
        s2 += wreg[o] * lW5[o * 512 + k];
    }
    int pk = (k & ~7) | perm_p(k & 7);  // permuted slot (matches GEMM output layout)
    g_wn[pk] = s1 * (1.f / 256.f);
    g_wl[pk] = s2;
    if (k == 0) {
        float b = 0.f;
        for (int o = 0; o < 256; ++o) b += nb5[o];
        g_sc[0] = b * (1.f / 256.f);
    }
    if (k == 1) {
        float b = 0.f;
        for (int o = 0; o < 256; ++o) b += wreg[o] * lb5[o];
        g_sc[1] = b;
    }
}

// ================= tf32 mma.sync GEMM v3 (K-permuted, LDS.64 fragments) =================
// Inputs A, W are tf32-rounded AND K-permuted. Outputs are written K-permuted
// (ready to be the next layer's A). ROUND=false keeps outputs full f32 (head inputs).
// CTA 128x128, BK=32, 256 threads (8 warps, 2x4, warp tile 64x32), 2 CTAs/SM.

#define PAD_STRIDE 40                    // words per 32-col row; 40 % 32 == 8 -> conflict-free LDS.64
#define MAT_WORDS  (128 * PAD_STRIDE)    // 5120 words
#define MAT_BYTES  (MAT_WORDS * 4)       // 20480 B
#define BUF_BYTES  (2 * MAT_BYTES)       // A + B per buffer: 40960 B
#define SMEM_BYTES (2 * BUF_BYTES)       // double-buffered: 81920 B

__device__ __forceinline__ void mma_tf32(float* c, const uint32_t* a, const uint32_t* b) {
    asm volatile(
        "mma.sync.aligned.m16n8k8.row.col.f32.tf32.tf32.f32 "
        "{%0,%1,%2,%3}, {%4,%5,%6,%7}, {%8,%9}, {%0,%1,%2,%3};"
        : "+f"(c[0]), "+f"(c[1]), "+f"(c[2]), "+f"(c[3])
        : "r"(a[0]), "r"(a[1]), "r"(a[2]), "r"(a[3]), "r"(b[0]), "r"(b[1]));
}

template <bool ROUND>
__global__ __launch_bounds__(256, 2)
void gemm_mma(const float* __restrict__ A, const float* __restrict__ W,
              const float* __restrict__ bias, float* __restrict__ C,
              int M, int N, int K)
{
    extern __shared__ float sm[];   // [buf][A|B][128][PAD_STRIDE]

    const int t    = threadIdx.x;
    const int lane = t & 31;
    const int wid  = t >> 5;
    const int bm   = blockIdx.y * 128;
    const int bn   = blockIdx.x * 128;
    const int wm   = (wid >> 2) * 64;   // warp M offset (0 or 64)
    const int wn   = (wid & 3) * 32;    // warp N offset (0,32,64,96)
    const int gid  = lane >> 2;         // 0..7
    const int tg   = lane & 3;          // 0..3

    // async-copy geometry: 1024 x 16B per matrix tile; 4 per thread per matrix
    const int g_row = t >> 3;           // base row 0..31 (+32*j)
    const int g_c4  = (t & 7) << 2;     // k word offset 0,4,...,28

    const uint32_t sbase = smem_u32(sm);
    const uint32_t d_off = (uint32_t)(g_row * PAD_STRIDE + g_c4) * 4;

    float acc[4][4][4] = {};            // [mi][ni][c0..c3]
    const int nkt = (K + 31) >> 5;

    auto cp_tile = [&](int kt, int buf) {
        const int k0 = kt << 5;
        const bool ok = (k0 + g_c4 + 3) < K;
        const int sz = ok ? 16 : 0;
        const int koff = ok ? (k0 + g_c4) : 0;       // safe base when zero-filling
        const uint32_t dA = sbase + buf * BUF_BYTES + d_off;
        const uint32_t dB = dA + MAT_BYTES;
        const float* Ap = A + (long)(bm + g_row) * K + koff;
        const float* Wp = W + (long)(bn + g_row) * K + koff;
        #pragma unroll
        for (int j = 0; j < 4; ++j) {
            cp16(dA + j * 32 * (PAD_STRIDE * 4), Ap + (long)j * 32 * K, sz);
            cp16(dB + j * 32 * (PAD_STRIDE * 4), Wp + (long)j * 32 * K, sz);
        }
    };

    // ---- prologue ----
    cp_tile(0, 0);
    CP_COMMIT();

    // ---- main loop ----
    for (int kt = 0; kt < nkt; ++kt) {
        const int buf = kt & 1;
        if (kt + 1 < nkt) {
            cp_tile(kt + 1, buf ^ 1);
            CP_COMMIT();
            CP_WAIT1();                 // current buffer's group complete
        } else {
            CP_WAIT0();
        }
        __syncthreads();

        const float* as = sm + buf * (BUF_BYTES / 4);
        const float* bs = as + MAT_WORDS;
        const int tg2 = tg << 1;

        #pragma unroll
        for (int ks = 0; ks < 4; ++ks) {
            const int kc = ks << 3;
            // permuted layout: word (kc+2tg) holds orig col kc+tg; (kc+2tg+1) holds kc+tg+4
            uint32_t af[4][4], bf[4][2];
            #pragma unroll
            for (int mi = 0; mi < 4; ++mi) {
                const int r0 = wm + (mi << 4) + gid;
                uint2 lo = *(const uint2*)(as + r0 * PAD_STRIDE + kc + tg2);
                uint2 hi = *(const uint2*)(as + (r0 + 8) * PAD_STRIDE + kc + tg2);
                af[mi][0] = lo.x; af[mi][1] = hi.x; af[mi][2] = lo.y; af[mi][3] = hi.y;
            }
            #pragma unroll
            for (int ni = 0; ni < 4; ++ni) {
                const int rn = wn + (ni << 3) + gid;
                uint2 bb = *(const uint2*)(bs + rn * PAD_STRIDE + kc + tg2);
                bf[ni][0] = bb.x; bf[ni][1] = bb.y;
            }
            #pragma unroll
            for (int mi = 0; mi < 4; ++mi)
                #pragma unroll
                for (int ni = 0; ni < 4; ++ni)
                    mma_tf32(acc[mi][ni], af[mi], bf[ni]);
        }
        __syncthreads();   // all reads of buf done before it is overwritten next iter
    }

    // ---- epilogue: bias + relu (+ tf32 round), scatter-store into permuted layout ----
    // logical cols c0 = base8 + 2tg, c1 = c0+1 -> permuted slots p0 = p[2tg], p1 = p0+2
    const int p0 = (tg < 2) ? (tg << 2) : ((tg << 2) - 7);
    #pragma unroll
    for (int mi = 0; mi < 4; ++mi) {
        const long row0 = bm + wm + (mi << 4) + gid;
        const long row1 = row0 + 8;
        #pragma unroll
        for (int ni = 0; ni < 4; ++ni) {
            const int base8 = bn + wn + (ni << 3);
            const float b0 = __ldg(bias + base8 + (tg << 1));
            const float b1 = __ldg(bias + base8 + (tg << 1) + 1);
            float v0 = fmaxf(acc[mi][ni][0] + b0, 0.f);
            float v1 = fmaxf(acc[mi][ni][1] + b1, 0.f);
            float v2 = fmaxf(acc[mi][ni][2] + b0, 0.f);
            float v3 = fmaxf(acc[mi][ni][3] + b1, 0.f);
            if (ROUND) { v0 = tf32r(v0); v1 = tf32r(v1); v2 = tf32r(v2); v3 = tf32r(v3); }
            C[row0 * N + base8 + p0]     = v0;
            C[row0 * N + base8 + p0 + 2] = v1;
            C[row1 * N + base8 + p0]     = v2;
            C[row1 * N + base8 + p0 + 2] = v3;
        }
    }
}

// ---------------- fused head: out[b] = (x4n[b].wn + bn) * (x4l[b].wl + bl) ----------------
// Both operand vectors are in the SAME permuted layout -> dot product unchanged.
__global__ __launch_bounds__(256)
void head_kernel(const float* __restrict__ xn, const float* __restrict__ xl,
                 float* __restrict__ out)
{
    int warp = (blockIdx.x * 256 + threadIdx.x) >> 5;
    int lane = threadIdx.x & 31;
    if (warp >= BATCH) return;

    const float4* pn = (const float4*)(xn + (long)warp * 512);
    const float4* pl = (const float4*)(xl + (long)warp * 512);
    const float4* wn = (const float4*)g_wn;
    const float4* wl = (const float4*)g_wl;

    float sn = 0.f, sl = 0.f;
    #pragma unroll
    for (int i = lane; i < 128; i += 32) {
        float4 a = pn[i], w = wn[i];
        sn += a.x * w.x + a.y * w.y + a.z * w.z + a.w * w.w;
        float4 b = pl[i], v = wl[i];
        sl += b.x * v.x + b.y * v.y + b.z * v.z + b.w * v.w;
    }
    #pragma unroll
    for (int off = 16; off > 0; off >>= 1) {
        sn += __shfl_xor_sync(0xffffffffu, sn, off);
        sl += __shfl_xor_sync(0xffffffffu, sl, off);
    }
    if (lane == 0)
        out[warp] = (sn + g_sc[0]) * (sl + g_sc[1]);
}

// ---------------- launch ----------------
static inline void cvt_launch(const float* src, float* dst, int n) {
    cvt_perm_kernel<<<(n + 255) / 256, 256>>>(src, dst, n);
}

extern "C" void kernel_launch(void* const* d_in, const int* in_sizes, int n_in,
                              void* d_out, int out_size)
{
    const float* node_x = (const float*)d_in[0];   // [B,256]
    const float* layer_x= (const float*)d_in[1];   // [B,16]
    const float* nW1 = (const float*)d_in[2];  const float* nb1 = (const float*)d_in[3];
    const float* nW2 = (const float*)d_in[4];  const float* nb2 = (const float*)d_in[5];
    const float* nW3 = (const float*)d_in[6];  const float* nb3 = (const float*)d_in[7];
    const float* nW4 = (const float*)d_in[8];  const float* nb4 = (const float*)d_in[9];
    const float* nW5 = (const float*)d_in[10]; const float* nb5 = (const float*)d_in[11];
    const float* lW1 = (const float*)d_in[12]; const float* lb1 = (const float*)d_in[13];
    const float* lW2 = (const float*)d_in[14]; const float* lb2 = (const float*)d_in[15];
    const float* lW3 = (const float*)d_in[16]; const float* lb3 = (const float*)d_in[17];
    const float* lW4 = (const float*)d_in[18]; const float* lb4 = (const float*)d_in[19];
    const float* lW5 = (const float*)d_in[20]; const float* lb5 = (const float*)d_in[21];
    const float* wreg= (const float*)d_in[22]; // [256]
    float* out = (float*)d_out;

    float *buf0, *buf1, *x4n, *xn, *xl, *wt;
    cudaGetSymbolAddress((void**)&buf0, g_buf0);
    cudaGetSymbolAddress((void**)&buf1, g_buf1);
    cudaGetSymbolAddress((void**)&x4n,  g_x4n);
    cudaGetSymbolAddress((void**)&xn,   g_xn);
    cudaGetSymbolAddress((void**)&xl,   g_xl);
    cudaGetSymbolAddress((void**)&wt,   g_wt);

    const int M = BATCH;
    cudaFuncSetAttribute(gemm_mma<true>,  cudaFuncAttributeMaxDynamicSharedMemorySize, SMEM_BYTES);
    cudaFuncSetAttribute(gemm_mma<false>, cudaFuncAttributeMaxDynamicSharedMemorySize, SMEM_BYTES);

    dim3 blk(256);

    precompute_head<<<1, 512>>>(nW5, nb5, lW5, lb5, wreg);

    // tf32-RNA + K-permute prepass: inputs + weights
    cvt_launch(node_x,  xn, BATCH * 256);
    cvt_launch(layer_x, xl, BATCH * 16);
    cvt_launch(nW1, wt + OFF_NW1, 256 * 256);
    cvt_launch(nW2, wt + OFF_NW2, 512 * 256);
    cvt_launch(nW3, wt + OFF_NW3, 1024 * 512);
    cvt_launch(nW4, wt + OFF_NW4, 512 * 1024);
    cvt_launch(lW1, wt + OFF_LW1, 256 * 16);
    cvt_launch(lW2, wt + OFF_LW2, 512 * 256);
    cvt_launch(lW3, wt + OFF_LW3, 1024 * 512);
    cvt_launch(lW4, wt + OFF_LW4, 512 * 1024);

    // node tower (relu after layers 1-4; layer 5 collapsed into head)
    gemm_mma<true ><<<dim3(256/128,  M/128), blk, SMEM_BYTES>>>(xn,   wt + OFF_NW1, nb1, buf0, M, 256, 256);
    gemm_mma<true ><<<dim3(512/128,  M/128), blk, SMEM_BYTES>>>(buf0, wt + OFF_NW2, nb2, buf1, M, 512, 256);
    gemm_mma<true ><<<dim3(1024/128, M/128), blk, SMEM_BYTES>>>(buf1, wt + OFF_NW3, nb3, buf0, M, 1024, 512);
    gemm_mma<false><<<dim3(512/128,  M/128), blk, SMEM_BYTES>>>(buf0, wt + OFF_NW4, nb4, x4n,  M, 512, 1024);

    // layer tower
    gemm_mma<true ><<<dim3(256/128,  M/128), blk, SMEM_BYTES>>>(xl,   wt + OFF_LW1, lb1, buf0, M, 256, 16);
    gemm_mma<true ><<<dim3(512/128,  M/128), blk, SMEM_BYTES>>>(buf0, wt + OFF_LW2, lb2, buf1, M, 512, 256);
    gemm_mma<true ><<<dim3(1024/128, M/128), blk, SMEM_BYTES>>>(buf1, wt + OFF_LW3, lb3, buf0, M, 1024, 512);
    gemm_mma<false><<<dim3(512/128,  M/128), blk, SMEM_BYTES>>>(buf0, wt + OFF_LW4, lb4, buf1, M, 512, 1024);

    // fused collapsed head
    head_kernel<<<(BATCH * 32) / 256, blk>>>(x4n, buf1, out);
}

// round 10
// speedup vs baseline: 1.0005x; 1.0005x over previous
#include <cuda_runtime.h>
#include <cstdint>

#define BATCH 32768

// ---------------- scratch (static device globals; no allocs allowed) ----------------
__device__ __align__(16) float g_buf0[BATCH * 1024];
__device__ __align__(16) float g_buf1[BATCH * 1024];
__device__ __align__(16) float g_x4n [BATCH * 512];
__device__ __align__(16) float g_xn  [BATCH * 256];   // tf32-rounded node_x
__device__ __align__(16) float g_xl  [BATCH * 16];    // tf32-rounded layer_x
__device__ __align__(16) float g_wt  [2428928];       // tf32-rounded weights (8 mats)
__device__ __align__(16) float g_wn[512];
__device__ __align__(16) float g_wl[512];
__device__ float g_sc[2];   // [0]=bn (mean of nb5), [1]=bl (wreg . lb5)

// weight offsets inside g_wt
#define OFF_NW1 0
#define OFF_NW2 65536
#define OFF_NW3 196608
#define OFF_NW4 720896
#define OFF_LW1 1245184
#define OFF_LW2 1249280
#define OFF_LW3 1380352
#define OFF_LW4 1904640

// cvt.rna.tf32.f32: destination is a .b32 register -> "=r".
__device__ __forceinline__ uint32_t f32_to_tf32_rna(float x) {
    uint32_t r;
    asm("cvt.rna.tf32.f32 %0, %1;" : "=r"(r) : "f"(x));
    return r;
}
__device__ __forceinline__ float tf32r(float x) {
    return __uint_as_float(f32_to_tf32_rna(x));
}

__device__ __forceinline__ uint32_t smem_u32(const void* p) {
    uint32_t a;
    asm("{ .reg .u64 t; cvta.to.shared.u64 t, %1; cvt.u32.u64 %0, t; }" : "=r"(a) : "l"(p));
    return a;
}

// cp.async 16B with register src-size (0 => zero-fill 16B)
__device__ __forceinline__ void cp16(uint32_t dst, const void* src, int src_size) {
    asm volatile("cp.async.cg.shared.global [%0], [%1], 16, %2;"
                 :: "r"(dst), "l"(src), "r"(src_size));
}
#define CP_COMMIT() asm volatile("cp.async.commit_group;" ::: "memory")
#define CP_WAIT0()  asm volatile("cp.async.wait_group 0;" ::: "memory")
#define CP_WAIT1()  asm volatile("cp.async.wait_group 1;" ::: "memory")

// ---------------- fused tf32-RNA rounding prepass (single launch) ----------------
struct CvtArgs {
    const float* src[10];
    float*       dst[10];
    int          n4[10];    // element count / 4
};

__global__ __launch_bounds__(256)
void cvt_all_kernel(CvtArgs a)
{
    const int tid    = blockIdx.x * 256 + threadIdx.x;
    const int stride = gridDim.x * 256;
    #pragma unroll
    for (int s = 0; s < 10; ++s) {
        const float4* sp = (const float4*)a.src[s];
        float4*       dp = (float4*)a.dst[s];
        const int n4 = a.n4[s];
        for (int i = tid; i < n4; i += stride) {
            float4 v = sp[i];
            v.x = tf32r(v.x); v.y = tf32r(v.y); v.z = tf32r(v.z); v.w = tf32r(v.w);
            dp[i] = v;
        }
    }
}

// ---------------- head-collapse precompute ----------------
// w_n[k] = mean_o nW5[o,k]; w_l[k] = sum_o wreg[o]*lW5[o,k]
__global__ void precompute_head(const float* __restrict__ nW5, const float* __restrict__ nb5,
                                const float* __restrict__ lW5, const float* __restrict__ lb5,
                                const float* __restrict__ wreg)
{
    int k = threadIdx.x;                // 512 threads
    float s1 = 0.f, s2 = 0.f;
    #pragma unroll 4
    for (int o = 0; o < 256; ++o) {
        s1 += nW5[o * 512 + k];
        s2 += wreg[o] * lW5[o * 512 + k];
    }
    g_wn[k] = s1 * (1.f / 256.f);
    g_wl[k] = s2;
    if (k == 0) {
        float b = 0.f;
        for (int o = 0; o < 256; ++o) b += nb5[o];
        g_sc[0] = b * (1.f / 256.f);
    }
    if (k == 1) {
        float b = 0.f;
        for (int o = 0; o < 256; ++o) b += wreg[o] * lb5[o];
        g_sc[1] = b;
    }
}

// ================= tf32 mma.sync GEMM v4 (3-stage cp.async, 1 sync/tile) ============
// C[M,N] = [tf32r](relu(A @ W^T + bias)); A, W pre-rounded tf32 bit patterns.
// CTA 128x128, BK=32, 256 threads (8 warps, 2x4, warp tile 64x32), 2 CTAs/SM.
// 3-stage pipeline: wait(<=1) -> sync -> prefetch kt+2 -> compute kt.

#define PAD_STRIDE 36                    // words per 32-col row (padded)
#define MAT_WORDS  (128 * PAD_STRIDE)    // 4608 words
#define MAT_BYTES  (MAT_WORDS * 4)       // 18432 B
#define BUF_BYTES  (2 * MAT_BYTES)       // A + B per buffer: 36864 B
#define NSTAGE     3
#define SMEM_BYTES (NSTAGE * BUF_BYTES)  // 110592 B

__device__ __forceinline__ void mma_tf32(float* c, const uint32_t* a, const uint32_t* b) {
    asm volatile(
        "mma.sync.aligned.m16n8k8.row.col.f32.tf32.tf32.f32 "
        "{%0,%1,%2,%3}, {%4,%5,%6,%7}, {%8,%9}, {%0,%1,%2,%3};"
        : "+f"(c[0]), "+f"(c[1]), "+f"(c[2]), "+f"(c[3])
        : "r"(a[0]), "r"(a[1]), "r"(a[2]), "r"(a[3]), "r"(b[0]), "r"(b[1]));
}

template <bool ROUND>
__global__ __launch_bounds__(256, 2)
void gemm_mma(const float* __restrict__ A, const float* __restrict__ W,
              const float* __restrict__ bias, float* __restrict__ C,
              int M, int N, int K)
{
    extern __shared__ float sm[];   // [stage][A|B][128][PAD_STRIDE]

    const int t    = threadIdx.x;
    const int lane = t & 31;
    const int wid  = t >> 5;
    const int bm   = blockIdx.y * 128;
    const int bn   = blockIdx.x * 128;
    const int wm   = (wid >> 2) * 64;   // warp M offset (0 or 64)
    const int wn   = (wid & 3) * 32;    // warp N offset (0,32,64,96)
    const int gid  = lane >> 2;         // 0..7
    const int tg   = lane & 3;          // 0..3

    // async-copy geometry: 1024 x 16B per matrix tile; 4 per thread per matrix
    const int g_row = t >> 3;           // base row 0..31 (+32*j)
    const int g_c4  = (t & 7) << 2;     // k word offset 0,4,...,28

    const uint32_t sbase = smem_u32(sm);
    const uint32_t d_off = (uint32_t)(g_row * PAD_STRIDE + g_c4) * 4;

    float acc[4][4][4] = {};            // [mi][ni][c0..c3]
    const int nkt = (K + 31) >> 5;

    auto cp_tile = [&](int kt, int buf) {
        const int k0 = kt << 5;
        const bool ok = (k0 + g_c4 + 3) < K;
        const int sz = ok ? 16 : 0;
        const int koff = ok ? (k0 + g_c4) : 0;       // safe base when zero-filling
        const uint32_t dA = sbase + buf * BUF_BYTES + d_off;
        const uint32_t dB = dA + MAT_BYTES;
        const float* Ap = A + (long)(bm + g_row) * K + koff;
        const float* Wp = W + (long)(bn + g_row) * K + koff;
        #pragma unroll
        for (int j = 0; j < 4; ++j) {
            cp16(dA + j * 32 * (PAD_STRIDE * 4), Ap + (long)j * 32 * K, sz);
            cp16(dB + j * 32 * (PAD_STRIDE * 4), Wp + (long)j * 32 * K, sz);
        }
    };

    // ---- prologue: stage tiles 0 and 1 ----
    cp_tile(0, 0);
    CP_COMMIT();
    if (1 < nkt) { cp_tile(1, 1); CP_COMMIT(); }

    int buf = 0;
    for (int kt = 0; kt < nkt; ++kt) {
        // tile kt complete when <=1 newer group pending (kt+1); at tail, 0.
        if (kt + 1 < nkt) CP_WAIT1(); else CP_WAIT0();
        __syncthreads();                 // data visible + tile kt-1 readers retired

        if (kt + 2 < nkt) {              // prefetch into buffer of retired tile kt-1
            cp_tile(kt + 2, (buf + 2 >= NSTAGE) ? (buf + 2 - NSTAGE) : (buf + 2));
            CP_COMMIT();
        }

        const float* as = sm + buf * (BUF_BYTES / 4);
        const float* bs = as + MAT_WORDS;

        #pragma unroll
        for (int ks = 0; ks < 4; ++ks) {
            const int kc = ks << 3;
            uint32_t af[4][4], bf[4][2];
            #pragma unroll
            for (int mi = 0; mi < 4; ++mi) {
                const int r0 = wm + (mi << 4) + gid;
                af[mi][0] = __float_as_uint(as[(r0    ) * PAD_STRIDE + kc + tg    ]);
                af[mi][1] = __float_as_uint(as[(r0 + 8) * PAD_STRIDE + kc + tg    ]);
                af[mi][2] = __float_as_uint(as[(r0    ) * PAD_STRIDE + kc + tg + 4]);
                af[mi][3] = __float_as_uint(as[(r0 + 8) * PAD_STRIDE + kc + tg + 4]);
            }
            #pragma unroll
            for (int ni = 0; ni < 4; ++ni) {
                const int rn = wn + (ni << 3) + gid;
                bf[ni][0] = __float_as_uint(bs[rn * PAD_STRIDE + kc + tg    ]);
                bf[ni][1] = __float_as_uint(bs[rn * PAD_STRIDE + kc + tg + 4]);
            }
            #pragma unroll
            for (int mi = 0; mi < 4; ++mi)
                #pragma unroll
                for (int ni = 0; ni < 4; ++ni)
                    mma_tf32(acc[mi][ni], af[mi], bf[ni]);
        }

        buf = (buf + 1 == NSTAGE) ? 0 : (buf + 1);
    }

    // ---- epilogue: bias + relu (+ tf32 round), float2 stores ----
    #pragma unroll
    for (int mi = 0; mi < 4; ++mi) {
        const long row0 = bm + wm + (mi << 4) + gid;
        const long row1 = row0 + 8;
        #pragma unroll
        for (int ni = 0; ni < 4; ++ni) {
            const int col = bn + wn + (ni << 3) + (tg << 1);
            const float b0 = __ldg(bias + col);
            const float b1 = __ldg(bias + col + 1);
            float2 lo, hi;
            lo.x = fmaxf(acc[mi][ni][0] + b0, 0.f);
            lo.y = fmaxf(acc[mi][ni][1] + b1, 0.f);
            hi.x = fmaxf(acc[mi][ni][2] + b0, 0.f);
            hi.y = fmaxf(acc[mi][ni][3] + b1, 0.f);
            if (ROUND) {
                lo.x = tf32r(lo.x); lo.y = tf32r(lo.y);
                hi.x = tf32r(hi.x); hi.y = tf32r(hi.y);
            }
            *(float2*)(C + row0 * N + col) = lo;
            *(float2*)(C + row1 * N + col) = hi;
        }
    }
}

// ---------------- fused head: out[b] = (x4n[b].wn + bn) * (x4l[b].wl + bl) ----------------
__global__ __launch_bounds__(256)
void head_kernel(const float* __restrict__ xn, const float* __restrict__ xl,
                 float* __restrict__ out)
{
    int warp = (blockIdx.x * 256 + threadIdx.x) >> 5;
    int lane = threadIdx.x & 31;
    if (warp >= BATCH) return;

    const float4* pn = (const float4*)(xn + (long)warp * 512);
    const float4* pl = (const float4*)(xl + (long)warp * 512);
    const float4* wn = (const float4*)g_wn;
    const float4* wl = (const float4*)g_wl;

    float sn = 0.f, sl = 0.f;
    #pragma unroll
    for (int i = lane; i < 128; i += 32) {
        float4 a = pn[i], w = wn[i];
        sn += a.x * w.x + a.y * w.y + a.z * w.z + a.w * w.w;
        float4 b = pl[i], v = wl[i];
        sl += b.x * v.x + b.y * v.y + b.z * v.z + b.w * v.w;
    }
    #pragma unroll
    for (int off = 16; off > 0; off >>= 1) {
        sn += __shfl_xor_sync(0xffffffffu, sn, off);
        sl += __shfl_xor_sync(0xffffffffu, sl, off);
    }
    if (lane == 0)
        out[warp] = (sn + g_sc[0]) * (sl + g_sc[1]);
}

// ---------------- launch ----------------
extern "C" void kernel_launch(void* const* d_in, const int* in_sizes, int n_in,
                              void* d_out, int out_size)
{
    const float* node_x = (const float*)d_in[0];   // [B,256]
    const float* layer_x= (const float*)d_in[1];   // [B,16]
    const float* nW1 = (const float*)d_in[2];  const float* nb1 = (const float*)d_in[3];
    const float* nW2 = (const float*)d_in[4];  const float* nb2 = (const float*)d_in[5];
    const float* nW3 = (const float*)d_in[6];  const float* nb3 = (const float*)d_in[7];
    const float* nW4 = (const float*)d_in[8];  const float* nb4 = (const float*)d_in[9];
    const float* nW5 = (const float*)d_in[10]; const float* nb5 = (const float*)d_in[11];
    const float* lW1 = (const float*)d_in[12]; const float* lb1 = (const float*)d_in[13];
    const float* lW2 = (const float*)d_in[14]; const float* lb2 = (const float*)d_in[15];
    const float* lW3 = (const float*)d_in[16]; const float* lb3 = (const float*)d_in[17];
    const float* lW4 = (const float*)d_in[18]; const float* lb4 = (const float*)d_in[19];
    const float* lW5 = (const float*)d_in[20]; const float* lb5 = (const float*)d_in[21];
    const float* wreg= (const float*)d_in[22]; // [256]
    float* out = (float*)d_out;

    float *buf0, *buf1, *x4n, *xn, *xl, *wt;
    cudaGetSymbolAddress((void**)&buf0, g_buf0);
    cudaGetSymbolAddress((void**)&buf1, g_buf1);
    cudaGetSymbolAddress((void**)&x4n,  g_x4n);
    cudaGetSymbolAddress((void**)&xn,   g_xn);
    cudaGetSymbolAddress((void**)&xl,   g_xl);
    cudaGetSymbolAddress((void**)&wt,   g_wt);

    const int M = BATCH;
    cudaFuncSetAttribute(gemm_mma<true>,  cudaFuncAttributeMaxDynamicSharedMemorySize, SMEM_BYTES);
    cudaFuncSetAttribute(gemm_mma<false>, cudaFuncAttributeMaxDynamicSharedMemorySize, SMEM_BYTES);

    dim3 blk(256);

    // launch 1: head precompute
    precompute_head<<<1, 512>>>(nW5, nb5, lW5, lb5, wreg);

    // launch 2: fused tf32-RNA prepass (inputs + weights)
    CvtArgs ca;
    ca.src[0] = node_x;  ca.dst[0] = xn;            ca.n4[0] = BATCH * 256 / 4;
    ca.src[1] = layer_x; ca.dst[1] = xl;            ca.n4[1] = BATCH * 16 / 4;
    ca.src[2] = nW1;     ca.dst[2] = wt + OFF_NW1;  ca.n4[2] = 256 * 256 / 4;
    ca.src[3] = nW2;     ca.dst[3] = wt + OFF_NW2;  ca.n4[3] = 512 * 256 / 4;
    ca.src[4] = nW3;     ca.dst[4] = wt + OFF_NW3;  ca.n4[4] = 1024 * 512 / 4;
    ca.src[5] = nW4;     ca.dst[5] = wt + OFF_NW4;  ca.n4[5] = 512 * 1024 / 4;
    ca.src[6] = lW1;     ca.dst[6] = wt + OFF_LW1;  ca.n4[6] = 256 * 16 / 4;
    ca.src[7] = lW2;     ca.dst[7] = wt + OFF_LW2;  ca.n4[7] = 512 * 256 / 4;
    ca.src[8] = lW3;     ca.dst[8] = wt + OFF_LW3;  ca.n4[8] = 1024 * 512 / 4;
    ca.src[9] = lW4;     ca.dst[9] = wt + OFF_LW4;  ca.n4[9] = 512 * 1024 / 4;
    cvt_all_kernel<<<2048, 256>>>(ca);

    // launches 3-6: node tower (relu layers 1-4; layer 5 collapsed into head)
    gemm_mma<true ><<<dim3(256/128,  M/128), blk, SMEM_BYTES>>>(xn,   wt + OFF_NW1, nb1, buf0, M, 256, 256);
    gemm_mma<true ><<<dim3(512/128,  M/128), blk, SMEM_BYTES>>>(buf0, wt + OFF_NW2, nb2, buf1, M, 512, 256);
    gemm_mma<true ><<<dim3(1024/128, M/128), blk, SMEM_BYTES>>>(buf1, wt + OFF_NW3, nb3, buf0, M, 1024, 512);
    gemm_mma<false><<<dim3(512/128,  M/128), blk, SMEM_BYTES>>>(buf0, wt + OFF_NW4, nb4, x4n,  M, 512, 1024);

    // launches 7-10: layer tower
    gemm_mma<true ><<<dim3(256/128,  M/128), blk, SMEM_BYTES>>>(xl,   wt + OFF_LW1, lb1, buf0, M, 256, 16);
    gemm_mma<true ><<<dim3(512/128,  M/128), blk, SMEM_BYTES>>>(buf0, wt + OFF_LW2, lb2, buf1, M, 512, 256);
    gemm_mma<true ><<<dim3(1024/128, M/128), blk, SMEM_BYTES>>>(buf1, wt + OFF_LW3, lb3, buf0, M, 1024, 512);
    gemm_mma<false><<<dim3(512/128,  M/128), blk, SMEM_BYTES>>>(buf0, wt + OFF_LW4, lb4, buf1, M, 512, 1024);

    // launch 11: fused collapsed head
    head_kernel<<<(BATCH * 32) / 256, blk>>>(x4n, buf1, out);
}

// round 12
// speedup vs baseline: 1.0187x; 1.0182x over previous
#include <cuda_runtime.h>
#include <cstdint>

#define BATCH 32768

// ---------------- scratch (static device globals; no allocs allowed) ----------------
__device__ __align__(16) float g_buf0[BATCH * 1024];
__device__ __align__(16) float g_buf1[BATCH * 1024];
__device__ __align__(16) float g_x4n [BATCH * 512];
__device__ __align__(16) float g_xn  [BATCH * 256];   // tf32-rounded node_x
__device__ __align__(16) float g_xl  [BATCH * 16];    // tf32-rounded layer_x
__device__ __align__(16) float g_wt  [2428928];       // tf32-rounded weights (8 mats)
__device__ __align__(16) float g_wn[512];
__device__ __align__(16) float g_wl[512];
__device__ float g_sc[2];   // [0]=bn (mean of nb5), [1]=bl (wreg . lb5)

// weight offsets inside g_wt
#define OFF_NW1 0
#define OFF_NW2 65536
#define OFF_NW3 196608
#define OFF_NW4 720896
#define OFF_LW1 1245184
#define OFF_LW2 1249280
#define OFF_LW3 1380352
#define OFF_LW4 1904640

// cvt.rna.tf32.f32: destination is a .b32 register -> "=r".
__device__ __forceinline__ uint32_t f32_to_tf32_rna(float x) {
    uint32_t r;
    asm("cvt.rna.tf32.f32 %0, %1;" : "=r"(r) : "f"(x));
    return r;
}
__device__ __forceinline__ float tf32r(float x) {
    return __uint_as_float(f32_to_tf32_rna(x));
}

__device__ __forceinline__ uint32_t smem_u32(const void* p) {
    uint32_t a;
    asm("{ .reg .u64 t; cvta.to.shared.u64 t, %1; cvt.u32.u64 %0, t; }" : "=r"(a) : "l"(p));
    return a;
}

// cp.async 16B with register src-size (0 => zero-fill 16B)
__device__ __forceinline__ void cp16(uint32_t dst, const void* src, int src_size) {
    asm volatile("cp.async.cg.shared.global [%0], [%1], 16, %2;"
                 :: "r"(dst), "l"(src), "r"(src_size));
}
#define CP_COMMIT() asm volatile("cp.async.commit_group;" ::: "memory")
#define CP_WAIT0()  asm volatile("cp.async.wait_group 0;" ::: "memory")
#define CP_WAIT1()  asm volatile("cp.async.wait_group 1;" ::: "memory")

// ldmatrix: 8x8 b16 tiles == 8x4 b32 tiles; lane l of consumer gets word (row l/4, col l%4).
__device__ __forceinline__ void ldsm_x4(uint32_t& r0, uint32_t& r1, uint32_t& r2, uint32_t& r3,
                                        uint32_t addr) {
    asm volatile("ldmatrix.sync.aligned.m8n8.x4.shared.b16 {%0,%1,%2,%3}, [%4];"
                 : "=r"(r0), "=r"(r1), "=r"(r2), "=r"(r3) : "r"(addr));
}
__device__ __forceinline__ void ldsm_x2(uint32_t& r0, uint32_t& r1, uint32_t addr) {
    asm volatile("ldmatrix.sync.aligned.m8n8.x2.shared.b16 {%0,%1}, [%2];"
                 : "=r"(r0), "=r"(r1) : "r"(addr));
}

// ---------------- fused tf32-RNA rounding prepass (single launch) ----------------
struct CvtArgs {
    const float* src[10];
    float*       dst[10];
    int          n4[10];    // element count / 4
};

__global__ __launch_bounds__(256)
void cvt_all_kernel(CvtArgs a)
{
    const int tid    = blockIdx.x * 256 + threadIdx.x;
    const int stride = gridDim.x * 256;
    #pragma unroll
    for (int s = 0; s < 10; ++s) {
        const float4* sp = (const float4*)a.src[s];
        float4*       dp = (float4*)a.dst[s];
        const int n4 = a.n4[s];
        for (int i = tid; i < n4; i += stride) {
            float4 v = sp[i];
            v.x = tf32r(v.x); v.y = tf32r(v.y); v.z = tf32r(v.z); v.w = tf32r(v.w);
            dp[i] = v;
        }
    }
}

// ---------------- head-collapse precompute ----------------
// w_n[k] = mean_o nW5[o,k]; w_l[k] = sum_o wreg[o]*lW5[o,k]
__global__ void precompute_head(const float* __restrict__ nW5, const float* __restrict__ nb5,
                                const float* __restrict__ lW5, const float* __restrict__ lb5,
                                const float* __restrict__ wreg)
{
    int k = threadIdx.x;                // 512 threads
    float s1 = 0.f, s2 = 0.f;
    #pragma unroll 4
    for (int o = 0; o < 256; ++o) {
        s1 += nW5[o * 512 + k];
        s2 += wreg[o] * lW5[o * 512 + k];
    }
    g_wn[k] = s1 * (1.f / 256.f);
    g_wl[k] = s2;
    if (k == 0) {
        float b = 0.f;
        for (int o = 0; o < 256; ++o) b += nb5[o];
        g_sc[0] = b * (1.f / 256.f);
    }
    if (k == 1) {
        float b = 0.f;
        for (int o = 0; o < 256; ++o) b += wreg[o] * lb5[o];
        g_sc[1] = b;
    }
}

// ================= tf32 mma.sync GEMM v5 (ldmatrix fragments) ============
// C[M,N] = [tf32r](relu(A @ W^T + bias)); A, W pre-rounded tf32 bit patterns.
// CTA 128x128, BK=32, 256 threads (8 warps, 2x4, warp tile 64x32), 2 CTAs/SM.
// 3-stage cp.async pipeline, 1 sync/tile; fragment loads via LDSM (8 per k8-step).

#define PAD_STRIDE 36                    // words per 32-col row; row stride 144B (16B-mult, LDSM conflict-free)
#define MAT_WORDS  (128 * PAD_STRIDE)    // 4608 words
#define MAT_BYTES  (MAT_WORDS * 4)       // 18432 B
#define BUF_BYTES  (2 * MAT_BYTES)       // A + B per buffer: 36864 B
#define NSTAGE     3
#define SMEM_BYTES (NSTAGE * BUF_BYTES)  // 110592 B

__device__ __forceinline__ void mma_tf32(float* c, const uint32_t* a, const uint32_t* b) {
    asm volatile(
        "mma.sync.aligned.m16n8k8.row.col.f32.tf32.tf32.f32 "
        "{%0,%1,%2,%3}, {%4,%5,%6,%7}, {%8,%9}, {%0,%1,%2,%3};"
        : "+f"(c[0]), "+f"(c[1]), "+f"(c[2]), "+f"(c[3])
        : "r"(a[0]), "r"(a[1]), "r"(a[2]), "r"(a[3]), "r"(b[0]), "r"(b[1]));
}

template <bool ROUND>
__global__ __launch_bounds__(256, 2)
void gemm_mma(const float* __restrict__ A, const float* __restrict__ W,
              const float* __restrict__ bias, float* __restrict__ C,
              int M, int N, int K)
{
    extern __shared__ float sm[];   // [stage][A|B][128][PAD_STRIDE]

    const int t    = threadIdx.x;
    const int lane = t & 31;
    const int wid  = t >> 5;
    const int bm   = blockIdx.y * 128;
    const int bn   = blockIdx.x * 128;
    const int wm   = (wid >> 2) * 64;   // warp M offset (0 or 64)
    const int wn   = (wid & 3) * 32;    // warp N offset (0,32,64,96)
    const int gid  = lane >> 2;         // 0..7
    const int tg   = lane & 3;          // 0..3

    // async-copy geometry: 1024 x 16B per matrix tile; 4 per thread per matrix
    const int g_row = t >> 3;           // base row 0..31 (+32*j)
    const int g_c4  = (t & 7) << 2;     // k word offset 0,4,...,28

    const uint32_t sbase = smem_u32(sm);
    const uint32_t d_off = (uint32_t)(g_row * PAD_STRIDE + g_c4) * 4;

    // ldmatrix per-lane address offsets (bytes, relative to matrix base)
    // A (.x4): row = wm+16*mi+(lane&15), col-half = (lane>>4)*4 words
    // B (.x2): row = wn+8*ni+(lane&7),  col-half = (lane&8)?4:0 words
    uint32_t a_off[4], b_off[4];
    {
        const int ar = lane & 15;
        const int ac = (lane >> 4) << 2;
        const int br = lane & 7;
        const int bc = (lane & 8) ? 4 : 0;
        #pragma unroll
        for (int mi = 0; mi < 4; ++mi)
            a_off[mi] = (uint32_t)(((wm + (mi << 4) + ar) * PAD_STRIDE + ac) * 4);
        #pragma unroll
        for (int ni = 0; ni < 4; ++ni)
            b_off[ni] = (uint32_t)(((wn + (ni << 3) + br) * PAD_STRIDE + bc) * 4);
    }

    float acc[4][4][4] = {};            // [mi][ni][c0..c3]
    const int nkt = (K + 31) >> 5;

    auto cp_tile = [&](int kt, int buf) {
        const int k0 = kt << 5;
        const bool ok = (k0 + g_c4 + 3) < K;
        const int sz = ok ? 16 : 0;
        const int koff = ok ? (k0 + g_c4) : 0;       // safe base when zero-filling
        const uint32_t dA = sbase + buf * BUF_BYTES + d_off;
        const uint32_t dB = dA + MAT_BYTES;
        const float* Ap = A + (long)(bm + g_row) * K + koff;
        const float* Wp = W + (long)(bn + g_row) * K + koff;
        #pragma unroll
        for (int j = 0; j < 4; ++j) {
            cp16(dA + j * 32 * (PAD_STRIDE * 4), Ap + (long)j * 32 * K, sz);
            cp16(dB + j * 32 * (PAD_STRIDE * 4), Wp + (long)j * 32 * K, sz);
        }
    };

    // ---- prologue: stage tiles 0 and 1 ----
    cp_tile(0, 0);
    CP_COMMIT();
    if (1 < nkt) { cp_tile(1, 1); CP_COMMIT(); }

    int buf = 0;
    for (int kt = 0; kt < nkt; ++kt) {
        // tile kt complete when <=1 newer group pending (kt+1); at tail, 0.
        if (kt + 1 < nkt) CP_WAIT1(); else CP_WAIT0();
        __syncthreads();                 // data visible + tile kt-1 readers retired

        if (kt + 2 < nkt) {              // prefetch into buffer of retired tile kt-1
            cp_tile(kt + 2, (buf + 2 >= NSTAGE) ? (buf + 2 - NSTAGE) : (buf + 2));
            CP_COMMIT();
        }

        const uint32_t as_u = sbase + buf * BUF_BYTES;
        const uint32_t bs_u = as_u + MAT_BYTES;

        #pragma unroll
        for (int ks = 0; ks < 4; ++ks) {
            const uint32_t kb = (uint32_t)(ks << 5);   // kc*4 bytes, kc = 8*ks
            uint32_t af[4][4], bf[4][2];
            #pragma unroll
            for (int mi = 0; mi < 4; ++mi)
                ldsm_x4(af[mi][0], af[mi][1], af[mi][2], af[mi][3], as_u + a_off[mi] + kb);
            #pragma unroll
            for (int ni = 0; ni < 4; ++ni)
                ldsm_x2(bf[ni][0], bf[ni][1], bs_u + b_off[ni] + kb);
            #pragma unroll
            for (int mi = 0; mi < 4; ++mi)
                #pragma unroll
                for (int ni = 0; ni < 4; ++ni)
                    mma_tf32(acc[mi][ni], af[mi], bf[ni]);
        }

        buf = (buf + 1 == NSTAGE) ? 0 : (buf + 1);
    }

    // ---- epilogue: bias + relu (+ tf32 round), float2 stores ----
    #pragma unroll
    for (int mi = 0; mi < 4; ++mi) {
        const long row0 = bm + wm + (mi << 4) + gid;
        const long row1 = row0 + 8;
        #pragma unroll
        for (int ni = 0; ni < 4; ++ni) {
            const int col = bn + wn + (ni << 3) + (tg << 1);
            const float b0 = __ldg(bias + col);
            const float b1 = __ldg(bias + col + 1);
            float2 lo, hi;
            lo.x = fmaxf(acc[mi][ni][0] + b0, 0.f);
            lo.y = fmaxf(acc[mi][ni][1] + b1, 0.f);
            hi.x = fmaxf(acc[mi][ni][2] + b0, 0.f);
            hi.y = fmaxf(acc[mi][ni][3] + b1, 0.f);
            if (ROUND) {
                lo.x = tf32r(lo.x); lo.y = tf32r(lo.y);
                hi.x = tf32r(hi.x); hi.y = tf32r(hi.y);
            }
            *(float2*)(C + row0 * N + col) = lo;
            *(float2*)(C + row1 * N + col) = hi;
        }
    }
}

// ---------------- fused head: out[b] = (x4n[b].wn + bn) * (x4l[b].wl + bl) ----------------
__global__ __launch_bounds__(256)
void head_kernel(const float* __restrict__ xn, const float* __restrict__ xl,
                 float* __restrict__ out)
{
    int warp = (blockIdx.x * 256 + threadIdx.x) >> 5;
    int lane = threadIdx.x & 31;
    if (warp >= BATCH) return;

    const float4* pn = (const float4*)(xn + (long)warp * 512);
    const float4* pl = (const float4*)(xl + (long)warp * 512);
    const float4* wn = (const float4*)g_wn;
    const float4* wl = (const float4*)g_wl;

    float sn = 0.f, sl = 0.f;
    #pragma unroll
    for (int i = lane; i < 128; i += 32) {
        float4 a = pn[i], w = wn[i];
        sn += a.x * w.x + a.y * w.y + a.z * w.z + a.w * w.w;
        float4 b = pl[i], v = wl[i];
        sl += b.x * v.x + b.y * v.y + b.z * v.z + b.w * v.w;
    }
    #pragma unroll
    for (int off = 16; off > 0; off >>= 1) {
        sn += __shfl_xor_sync(0xffffffffu, sn, off);
        sl += __shfl_xor_sync(0xffffffffu, sl, off);
    }
    if (lane == 0)
        out[warp] = (sn + g_sc[0]) * (sl + g_sc[1]);
}

// ---------------- launch ----------------
extern "C" void kernel_launch(void* const* d_in, const int* in_sizes, int n_in,
                              void* d_out, int out_size)
{
    const float* node_x = (const float*)d_in[0];   // [B,256]
    const float* layer_x= (const float*)d_in[1];   // [B,16]
    const float* nW1 = (const float*)d_in[2];  const float* nb1 = (const float*)d_in[3];
    const float* nW2 = (const float*)d_in[4];  const float* nb2 = (const float*)d_in[5];
    const float* nW3 = (const float*)d_in[6];  const float* nb3 = (const float*)d_in[7];
    const float* nW4 = (const float*)d_in[8];  const float* nb4 = (const float*)d_in[9];
    const float* nW5 = (const float*)d_in[10]; const float* nb5 = (const float*)d_in[11];
    const float* lW1 = (const float*)d_in[12]; const float* lb1 = (const float*)d_in[13];
    const float* lW2 = (const float*)d_in[14]; const float* lb2 = (const float*)d_in[15];
    const float* lW3 = (const float*)d_in[16]; const float* lb3 = (const float*)d_in[17];
    const float* lW4 = (const float*)d_in[18]; const float* lb4 = (const float*)d_in[19];
    const float* lW5 = (const float*)d_in[20]; const float* lb5 = (const float*)d_in[21];
    const float* wreg= (const float*)d_in[22]; // [256]
    float* out = (float*)d_out;

    float *buf0, *buf1, *x4n, *xn, *xl, *wt;
    cudaGetSymbolAddress((void**)&buf0, g_buf0);
    cudaGetSymbolAddress((void**)&buf1, g_buf1);
    cudaGetSymbolAddress((void**)&x4n,  g_x4n);
    cudaGetSymbolAddress((void**)&xn,   g_xn);
    cudaGetSymbolAddress((void**)&xl,   g_xl);
    cudaGetSymbolAddress((void**)&wt,   g_wt);

    const int M = BATCH;
    cudaFuncSetAttribute(gemm_mma<true>,  cudaFuncAttributeMaxDynamicSharedMemorySize, SMEM_BYTES);
    cudaFuncSetAttribute(gemm_mma<false>, cudaFuncAttributeMaxDynamicSharedMemorySize, SMEM_BYTES);

    dim3 blk(256);

    // launch 1: head precompute
    precompute_head<<<1, 512>>>(nW5, nb5, lW5, lb5, wreg);

    // launch 2: fused tf32-RNA prepass (inputs + weights)
    CvtArgs ca;
    ca.src[0] = node_x;  ca.dst[0] = xn;            ca.n4[0] = BATCH * 256 / 4;
    ca.src[1] = layer_x; ca.dst[1] = xl;            ca.n4[1] = BATCH * 16 / 4;
    ca.src[2] = nW1;     ca.dst[2] = wt + OFF_NW1;  ca.n4[2] = 256 * 256 / 4;
    ca.src[3] = nW2;     ca.dst[3] = wt + OFF_NW2;  ca.n4[3] = 512 * 256 / 4;
    ca.src[4] = nW3;     ca.dst[4] = wt + OFF_NW3;  ca.n4[4] = 1024 * 512 / 4;
    ca.src[5] = nW4;     ca.dst[5] = wt + OFF_NW4;  ca.n4[5] = 512 * 1024 / 4;
    ca.src[6] = lW1;     ca.dst[6] = wt + OFF_LW1;  ca.n4[6] = 256 * 16 / 4;
    ca.src[7] = lW2;     ca.dst[7] = wt + OFF_LW2;  ca.n4[7] = 512 * 256 / 4;
    ca.src[8] = lW3;     ca.dst[8] = wt + OFF_LW3;  ca.n4[8] = 1024 * 512 / 4;
    ca.src[9] = lW4;     ca.dst[9] = wt + OFF_LW4;  ca.n4[9] = 512 * 1024 / 4;
    cvt_all_kernel<<<2048, 256>>>(ca);

    // launches 3-6: node tower (relu layers 1-4; layer 5 collapsed into head)
    gemm_mma<true ><<<dim3(256/128,  M/128), blk, SMEM_BYTES>>>(xn,   wt + OFF_NW1, nb1, buf0, M, 256, 256);
    gemm_mma<true ><<<dim3(512/128,  M/128), blk, SMEM_BYTES>>>(buf0, wt + OFF_NW2, nb2, buf1, M, 512, 256);
    gemm_mma<true ><<<dim3(1024/128, M/128), blk, SMEM_BYTES>>>(buf1, wt + OFF_NW3, nb3, buf0, M, 1024, 512);
    gemm_mma<false><<<dim3(512/128,  M/128), blk, SMEM_BYTES>>>(buf0, wt + OFF_NW4, nb4, x4n,  M, 512, 1024);

    // launches 7-10: layer tower
    gemm_mma<true ><<<dim3(256/128,  M/128), blk, SMEM_BYTES>>>(xl,   wt + OFF_LW1, lb1, buf0, M, 256, 16);
    gemm_mma<true ><<<dim3(512/128,  M/128), blk, SMEM_BYTES>>>(buf0, wt + OFF_LW2, lb2, buf1, M, 512, 256);
    gemm_mma<true ><<<dim3(1024/128, M/128), blk, SMEM_BYTES>>>(buf1, wt + OFF_LW3, lb3, buf0, M, 1024, 512);
    gemm_mma<false><<<dim3(512/128,  M/128), blk, SMEM_BYTES>>>(buf0, wt + OFF_LW4, lb4, buf1, M, 512, 1024);

    // launch 11: fused collapsed head
    head_kernel<<<(BATCH * 32) / 256, blk>>>(x4n, buf1, out);
}